// round 11
// baseline (speedup 1.0000x reference)
#include <cuda_runtime.h>
#include <math.h>

#define CIN 2048
#define NB  64
#define NK  32
#define DI  8
#define DO  16
#define EPSQ 1e-7f
#define CPB 16            // c per block

typedef unsigned long long ull;

// ---- scratch ----
__device__ float g_xT3[CIN * DI * NB];           // xT3[c][j][b] (4 MB)
__device__ float g_s  [NB * NK * DO];            // s accumulator
__device__ float g_v1 [NB * NK * DO];            // v after iter 1
__device__ float g_a  [(size_t)NK * CIN * NB];   // aT[k][c][b] -> cc (16 MB)

// ---- f32x2 helpers ----
__device__ __forceinline__ void fma2(ull& d, ull a, ull b) {
    asm("fma.rn.f32x2 %0, %1, %2, %0;" : "+l"(d) : "l"(a), "l"(b));
}
__device__ __forceinline__ ull pack2(float lo, float hi) {
    ull r; asm("mov.b64 %0, {%1, %2};" : "=l"(r) : "f"(lo), "f"(hi)); return r;
}
__device__ __forceinline__ float2 unpack2(ull v) {
    float2 f; asm("mov.b64 {%0, %1}, %2;" : "=f"(f.x), "=f"(f.y) : "l"(v)); return f;
}

// xT3[(c*8+j)*64+b] = x[b][c][j]; also zero g_s
__global__ void k_transposeZ(const float* __restrict__ x) {
    int idx = blockIdx.x * blockDim.x + threadIdx.x;
    if (idx < CIN * DI * NB) {
        int b = idx & 63, j = (idx >> 6) & 7, c = idx >> 9;
        g_xT3[idx] = __ldg(&x[(b * CIN + c) * DI + j]);
    }
    if (idx < NB * NK * DO) g_s[idx] = 0.f;
}

// Stage x-slice (16c x 512 floats, contiguous) and W tile [16c][16i][8j]->sW[c][j][i]
__device__ __forceinline__ void stage_tiles(float* sX, float* sW,
                                            const float* __restrict__ W,
                                            int k, int c0) {
    const float4* xs = (const float4*)(g_xT3 + (size_t)c0 * (DI * NB));
    float4* xd = (float4*)sX;
#pragma unroll
    for (int r = 0; r < 8; r++)
        xd[threadIdx.x + 256 * r] = __ldg(&xs[threadIdx.x + 256 * r]);
    const float4* ws = (const float4*)(W + ((size_t)k * CIN + c0) * (DO * DI));
#pragma unroll
    for (int r = 0; r < 2; r++) {
        int idx = threadIdx.x + 256 * r;            // 512 float4
        float4 v = __ldg(&ws[idx]);
        int c = idx >> 5, i = (idx >> 1) & 15, jq = idx & 1;
        float* d = &sW[c * 128 + i];
        d[(4 * jq + 0) * 16] = v.x;
        d[(4 * jq + 1) * 16] = v.y;
        d[(4 * jq + 2) * 16] = v.z;
        d[(4 * jq + 3) * 16] = v.w;
    }
}

// reduce acc[4][4] across 8 warps via rB (reuses sX; i-major [w][i][b]) -> g_s
__device__ __forceinline__ void block_reduce_s(float* rB, ull acc[4][4],
                                               int w, int b0, int ih, int k) {
    __syncthreads();                                // sX compute done
#pragma unroll
    for (int bi = 0; bi < 4; bi++)
#pragma unroll
        for (int p = 0; p < 4; p++) {
            float2 f = unpack2(acc[bi][p]);
            int i0 = 8 * ih + 2 * p;
            rB[w * 1024 + i0 * 64 + b0 + bi]       = f.x;
            rB[w * 1024 + (i0 + 1) * 64 + b0 + bi] = f.y;
        }
    __syncthreads();
#pragma unroll
    for (int r = 0; r < 4; r++) {
        int u = threadIdx.x + 256 * r;              // 1024 outputs (i,b)
        int i = u >> 6, b = u & 63;
        float s = 0.f;
#pragma unroll
        for (int w2 = 0; w2 < 8; w2++)
            s += rB[w2 * 1024 + i * 64 + b];
        atomicAdd(&g_s[(b * NK + k) * DO + i], s);
    }
}

// ---------- Pass A: s1[b,k,i] = sum_{c,j} W x ----------
__global__ void __launch_bounds__(256, 4) k_passA(const float* __restrict__ W) {
    __shared__ __align__(16) float sX[CPB * DI * NB];   // 8192 floats (also reduce buf)
    __shared__ __align__(16) float sW[CPB * DI * DO];   // 2048 floats
    int k = blockIdx.y, c0 = blockIdx.x * CPB;
    stage_tiles(sX, sW, W, k, c0);
    __syncthreads();

    int lane = threadIdx.x & 31, w = threadIdx.x >> 5;
    int bq = lane & 15, ih = lane >> 4;
    int b0 = 4 * bq;

    ull acc[4][4];
#pragma unroll
    for (int bi = 0; bi < 4; bi++)
#pragma unroll
        for (int p = 0; p < 4; p++) acc[bi][p] = 0ull;

#pragma unroll
    for (int it = 0; it < 2; it++) {
        int cl = 2 * w + it;
        const float* wb = &sW[cl * 128 + 8 * ih];
        const float4* xb = (const float4*)&sX[cl * (DI * NB) + b0];
#pragma unroll
        for (int j = 0; j < 8; j++) {
            float4 xv = xb[j * 16];
            ull xx0 = pack2(xv.x, xv.x), xx1 = pack2(xv.y, xv.y);
            ull xx2 = pack2(xv.z, xv.z), xx3 = pack2(xv.w, xv.w);
            const ulonglong2* wp = (const ulonglong2*)(wb + j * 16);
            ulonglong2 wA = wp[0], wB = wp[1];
            fma2(acc[0][0], wA.x, xx0); fma2(acc[0][1], wA.y, xx0);
            fma2(acc[0][2], wB.x, xx0); fma2(acc[0][3], wB.y, xx0);
            fma2(acc[1][0], wA.x, xx1); fma2(acc[1][1], wA.y, xx1);
            fma2(acc[1][2], wB.x, xx1); fma2(acc[1][3], wB.y, xx1);
            fma2(acc[2][0], wA.x, xx2); fma2(acc[2][1], wA.y, xx2);
            fma2(acc[2][2], wB.x, xx2); fma2(acc[2][3], wB.y, xx2);
            fma2(acc[3][0], wA.x, xx3); fma2(acc[3][1], wA.y, xx3);
            fma2(acc[3][2], wB.x, xx3); fma2(acc[3][3], wB.y, xx3);
        }
    }
    block_reduce_s(sX, acc, w, b0, ih, k);
}

// v1 = squash(s/32)
__global__ void k_squash1() {
    int t = blockIdx.x * blockDim.x + threadIdx.x;
    if (t >= NB * NK) return;
    float s[DO]; float sq = 0.f;
#pragma unroll
    for (int i = 0; i < DO; i++) { s[i] = g_s[t * DO + i] * (1.f / 32.f); sq += s[i] * s[i]; }
    float scale = (sq / (1.f + sq)) * rsqrtf(sq + EPSQ);
#pragma unroll
    for (int i = 0; i < DO; i++) g_v1[t * DO + i] = s[i] * scale;
}

// ---------- Pass C: aT[k][c][b] = sum_i u * v1 ----------
__global__ void __launch_bounds__(256, 4) k_passC(const float* __restrict__ W) {
    __shared__ __align__(16) float sX[CPB * DI * NB];
    __shared__ __align__(16) float sW[CPB * DI * DO];
    int k = blockIdx.y, c0 = blockIdx.x * CPB;
    stage_tiles(sX, sW, W, k, c0);
    __syncthreads();

    int lane = threadIdx.x & 31, w = threadIdx.x >> 5;
    int bq = lane & 15, ih = lane >> 4;
    int bh = w & 1, cw = w >> 1;
    int b0 = bh * 32 + 2 * bq;                      // 2 b per lane

    ull v2[2][4];
#pragma unroll
    for (int bi = 0; bi < 2; bi++) {
        const ull* vp = (const ull*)&g_v1[((b0 + bi) * NK + k) * DO + 8 * ih];
#pragma unroll
        for (int p = 0; p < 4; p++) v2[bi][p] = vp[p];
    }

#pragma unroll
    for (int it = 0; it < 4; it++) {
        int cl = cw + 4 * it;
        const float* wb = &sW[cl * 128 + 8 * ih];
        const float* xbase = &sX[cl * (DI * NB) + b0];

        ull u2[2][4];
#pragma unroll
        for (int bi = 0; bi < 2; bi++)
#pragma unroll
            for (int p = 0; p < 4; p++) u2[bi][p] = 0ull;

#pragma unroll
        for (int j = 0; j < 8; j++) {
            float2 xv = *(const float2*)(xbase + j * NB);
            ull xx0 = pack2(xv.x, xv.x), xx1 = pack2(xv.y, xv.y);
            const ulonglong2* wp = (const ulonglong2*)(wb + j * 16);
            ulonglong2 wA = wp[0], wB = wp[1];
            fma2(u2[0][0], wA.x, xx0); fma2(u2[0][1], wA.y, xx0);
            fma2(u2[0][2], wB.x, xx0); fma2(u2[0][3], wB.y, xx0);
            fma2(u2[1][0], wA.x, xx1); fma2(u2[1][1], wA.y, xx1);
            fma2(u2[1][2], wB.x, xx1); fma2(u2[1][3], wB.y, xx1);
        }
        ull d0 = 0ull, d1 = 0ull;
#pragma unroll
        for (int p = 0; p < 4; p++) {
            fma2(d0, u2[0][p], v2[0][p]);
            fma2(d1, u2[1][p], v2[1][p]);
        }
        float2 f0 = unpack2(d0), f1 = unpack2(d1);
        float a0 = f0.x + f0.y, a1 = f1.x + f1.y;   // partial (this i-half)
        a0 += __shfl_xor_sync(0xFFFFFFFFu, a0, 16);
        a1 += __shfl_xor_sync(0xFFFFFFFFu, a1, 16);
        if (ih == 0) {
            *(float2*)&g_a[((size_t)k * CIN + (c0 + cl)) * NB + b0] =
                make_float2(a0, a1);
        }
    }
}

// softmax over k at each (c,b), in place; also re-zeros g_s
__global__ void k_softmaxZ() {
    int idx = blockIdx.x * blockDim.x + threadIdx.x;
    if (idx < NB * NK * DO) g_s[idx] = 0.f;
    if (idx >= CIN * NB) return;
    float vals[NK]; float mx = -1e30f;
#pragma unroll
    for (int k = 0; k < NK; k++) {
        vals[k] = g_a[(size_t)k * (CIN * NB) + idx];
        mx = fmaxf(mx, vals[k]);
    }
    float sum = 0.f;
#pragma unroll
    for (int k = 0; k < NK; k++) { vals[k] = __expf(vals[k] - mx); sum += vals[k]; }
    float inv = 1.f / sum;
#pragma unroll
    for (int k = 0; k < NK; k++) g_a[(size_t)k * (CIN * NB) + idx] = vals[k] * inv;
}

// ---------- Pass E: s2[b,k,i] = sum_{c,j} W (cc x) ----------
__global__ void __launch_bounds__(256, 4) k_passE(const float* __restrict__ W) {
    __shared__ __align__(16) float sX[CPB * DI * NB];
    __shared__ __align__(16) float sW[CPB * DI * DO];
    int k = blockIdx.y, c0 = blockIdx.x * CPB;
    stage_tiles(sX, sW, W, k, c0);
    __syncthreads();

    int lane = threadIdx.x & 31, w = threadIdx.x >> 5;
    int bq = lane & 15, ih = lane >> 4;
    int b0 = 4 * bq;

    ull acc[4][4];
#pragma unroll
    for (int bi = 0; bi < 4; bi++)
#pragma unroll
        for (int p = 0; p < 4; p++) acc[bi][p] = 0ull;

#pragma unroll
    for (int it = 0; it < 2; it++) {
        int cl = 2 * w + it;
        int c  = c0 + cl;
        const float* wb = &sW[cl * 128 + 8 * ih];
        const float4* xb = (const float4*)&sX[cl * (DI * NB) + b0];
        float4 cc = *(const float4*)&g_a[((size_t)k * CIN + c) * NB + b0];
#pragma unroll
        for (int j = 0; j < 8; j++) {
            float4 xv = xb[j * 16];
            float m0 = xv.x * cc.x, m1 = xv.y * cc.y;
            float m2 = xv.z * cc.z, m3 = xv.w * cc.w;
            ull xx0 = pack2(m0, m0), xx1 = pack2(m1, m1);
            ull xx2 = pack2(m2, m2), xx3 = pack2(m3, m3);
            const ulonglong2* wp = (const ulonglong2*)(wb + j * 16);
            ulonglong2 wA = wp[0], wB = wp[1];
            fma2(acc[0][0], wA.x, xx0); fma2(acc[0][1], wA.y, xx0);
            fma2(acc[0][2], wB.x, xx0); fma2(acc[0][3], wB.y, xx0);
            fma2(acc[1][0], wA.x, xx1); fma2(acc[1][1], wA.y, xx1);
            fma2(acc[1][2], wB.x, xx1); fma2(acc[1][3], wB.y, xx1);
            fma2(acc[2][0], wA.x, xx2); fma2(acc[2][1], wA.y, xx2);
            fma2(acc[2][2], wB.x, xx2); fma2(acc[2][3], wB.y, xx2);
            fma2(acc[3][0], wA.x, xx3); fma2(acc[3][1], wA.y, xx3);
            fma2(acc[3][2], wB.x, xx3); fma2(acc[3][3], wB.y, xx3);
        }
    }
    block_reduce_s(sX, acc, w, b0, ih, k);
}

// out = squash(s2)
__global__ void k_squashF(float* __restrict__ out) {
    int t = blockIdx.x * blockDim.x + threadIdx.x;
    if (t >= NB * NK) return;
    float s[DO]; float sq = 0.f;
#pragma unroll
    for (int i = 0; i < DO; i++) { s[i] = g_s[t * DO + i]; sq += s[i] * s[i]; }
    float scale = (sq / (1.f + sq)) * rsqrtf(sq + EPSQ);
#pragma unroll
    for (int i = 0; i < DO; i++) out[t * DO + i] = s[i] * scale;
}

extern "C" void kernel_launch(void* const* d_in, const int* in_sizes, int n_in,
                              void* d_out, int out_size) {
    const float* x = (const float*)d_in[0];
    const float* W = (const float*)d_in[1];
    if (n_in >= 2 && in_sizes[0] == 8388608 && in_sizes[1] == 1048576) {
        const float* t = x; x = W; W = t;   // defensive order swap
    }
    float* out = (float*)d_out;

    dim3 passGrid(CIN / CPB, NK);   // (128, 32)
    dim3 passBlk(256);

    k_transposeZ<<<(CIN * DI * NB + 255) / 256, 256>>>(x);  // 1
    k_passA     <<<passGrid, passBlk>>>(W);                 // 2
    k_squash1   <<<(NB * NK + 127) / 128, 128>>>();         // 3
    k_passC     <<<passGrid, passBlk>>>(W);                 // 4  <- ncu capture
    k_softmaxZ  <<<(CIN * NB + 255) / 256, 256>>>();        // 5
    k_passE     <<<passGrid, passBlk>>>(W);                 // 6
    k_squashF   <<<(NB * NK + 127) / 128, 128>>>(out);      // 7
}

// round 12
// speedup vs baseline: 2.7908x; 2.7908x over previous
#include <cuda_runtime.h>
#include <math.h>

#define CIN 2048
#define NB  64
#define NK  32
#define DI  8
#define DO  16
#define EPSQ 1e-7f
#define CPB 64            // c per block
#define CSTRIDE 132       // smem stride per c for W tile (floats)

typedef unsigned long long ull;

// ---- scratch ----
__device__ float g_xT3[CIN * DI * NB];           // xT3[c][j][b] (4 MB)
__device__ float g_s  [NB * NK * DO];            // s accumulator
__device__ float g_a  [(size_t)NK * CIN * NB];   // aT[k][c][b] -> cc (16 MB)

// ---- f32x2 helpers ----
__device__ __forceinline__ void fma2(ull& d, ull a, ull b) {
    asm("fma.rn.f32x2 %0, %1, %2, %0;" : "+l"(d) : "l"(a), "l"(b));
}
__device__ __forceinline__ ull pack2(float lo, float hi) {
    ull r; asm("mov.b64 %0, {%1, %2};" : "=l"(r) : "f"(lo), "f"(hi)); return r;
}
__device__ __forceinline__ float2 unpack2(ull v) {
    float2 f; asm("mov.b64 {%0, %1}, %2;" : "=f"(f.x), "=f"(f.y) : "l"(v)); return f;
}

__global__ void k_zeroS() {
    int t = blockIdx.x * blockDim.x + threadIdx.x;
    if (t < NB * NK * DO) g_s[t] = 0.f;
}

// xT3[(c*8+j)*64+b] = x[b][c][j]
__global__ void k_transpose(const float* __restrict__ x) {
    int idx = blockIdx.x * blockDim.x + threadIdx.x;
    if (idx < CIN * DI * NB) {
        int b = idx & 63, j = (idx >> 6) & 7, c = idx >> 9;
        g_xT3[idx] = __ldg(&x[(b * CIN + c) * DI + j]);
    }
}

// Load W tile [64c][16i][8j] -> sW[c][j][i] (stride CSTRIDE)
__device__ __forceinline__ void load_w_tile(float* sW, const float* __restrict__ W,
                                            int k, int c0) {
    const float4* src = (const float4*)(W + ((size_t)k * CIN + c0) * (DO * DI));
#pragma unroll
    for (int r = 0; r < 8; r++) {
        int idx = threadIdx.x + r * 256;            // 2048 float4
        float4 v = __ldg(&src[idx]);
        int cp = idx >> 5, i = (idx >> 1) & 15, jq = idx & 1;
        float* d = &sW[cp * CSTRIDE + i];
        d[(4 * jq + 0) * 16] = v.x;
        d[(4 * jq + 1) * 16] = v.y;
        d[(4 * jq + 2) * 16] = v.z;
        d[(4 * jq + 3) * 16] = v.w;
    }
}

// block reduce acc[4][4] (4 b, one i-half) across 8 warps -> atomicAdd into g_s
__device__ __forceinline__ void block_reduce_s(float* sb, ull acc[4][4],
                                               int w, int b0, int ih, int k) {
    __syncthreads();
#pragma unroll
    for (int bi = 0; bi < 4; bi++) {
        float* row = &sb[(w * NB + b0 + bi) * 17 + 8 * ih];
#pragma unroll
        for (int p = 0; p < 4; p++) {
            float2 f = unpack2(acc[bi][p]);
            row[2 * p]     = f.x;
            row[2 * p + 1] = f.y;
        }
    }
    __syncthreads();
#pragma unroll
    for (int r = 0; r < 4; r++) {
        int u = threadIdx.x + 256 * r;              // 1024 outputs (b,i)
        int b = u >> 4, i = u & 15;
        float s = 0.f;
#pragma unroll
        for (int w2 = 0; w2 < 8; w2++)
            s += sb[(w2 * NB + b) * 17 + i];
        atomicAdd(&g_s[(b * NK + k) * DO + i], s);
    }
}

// ---------- Pass A: s1[b,k,i] = sum_{c,j} W x ----------
__global__ void __launch_bounds__(256) k_passA(const float* __restrict__ W) {
    __shared__ __align__(16) float sb[8704];
    int k = blockIdx.y, c0 = blockIdx.x * CPB;
    load_w_tile(sb, W, k, c0);
    __syncthreads();

    int lane = threadIdx.x & 31, w = threadIdx.x >> 5;
    int bq = lane & 15, ih = lane >> 4;
    int b0 = 4 * bq;

    ull acc[4][4];
#pragma unroll
    for (int bi = 0; bi < 4; bi++)
#pragma unroll
        for (int p = 0; p < 4; p++) acc[bi][p] = 0ull;

#pragma unroll
    for (int it = 0; it < 8; it++) {
        int cl = 8 * w + it;
        int c  = c0 + cl;
        const float* wbase = &sb[cl * CSTRIDE + 8 * ih];
        const float4* xbase = (const float4*)&g_xT3[(size_t)c * (DI * NB) + b0];
#pragma unroll
        for (int j = 0; j < 8; j++) {
            float4 xv = xbase[j * 16];
            ull xx0 = pack2(xv.x, xv.x), xx1 = pack2(xv.y, xv.y);
            ull xx2 = pack2(xv.z, xv.z), xx3 = pack2(xv.w, xv.w);
            const ulonglong2* wp = (const ulonglong2*)(wbase + j * 16);
            ulonglong2 wA = wp[0], wB = wp[1];
            fma2(acc[0][0], wA.x, xx0); fma2(acc[0][1], wA.y, xx0);
            fma2(acc[0][2], wB.x, xx0); fma2(acc[0][3], wB.y, xx0);
            fma2(acc[1][0], wA.x, xx1); fma2(acc[1][1], wA.y, xx1);
            fma2(acc[1][2], wB.x, xx1); fma2(acc[1][3], wB.y, xx1);
            fma2(acc[2][0], wA.x, xx2); fma2(acc[2][1], wA.y, xx2);
            fma2(acc[2][2], wB.x, xx2); fma2(acc[2][3], wB.y, xx2);
            fma2(acc[3][0], wA.x, xx3); fma2(acc[3][1], wA.y, xx3);
            fma2(acc[3][2], wB.x, xx3); fma2(acc[3][3], wB.y, xx3);
        }
    }
    block_reduce_s(sb, acc, w, b0, ih, k);
}

// ---------- Pass C: aT[k][c][b] = sum_i u * v1   (v1 computed in prologue) ----------
__global__ void __launch_bounds__(256) k_passC(const float* __restrict__ W) {
    __shared__ __align__(16) float sW[CPB * CSTRIDE];   // 8448 floats
    __shared__ __align__(16) float sV[NB * 18];         // squashed v1, stride 18
    int k = blockIdx.y, c0 = blockIdx.x * CPB;
    load_w_tile(sW, W, k, c0);

    // prologue: v1[b] = squash(s1[b,k]/32) into sV
    if (threadIdx.x < NB) {
        int b = threadIdx.x;
        const float4* sp = (const float4*)&g_s[(b * NK + k) * DO];
        float s[DO]; float sq = 0.f;
#pragma unroll
        for (int q = 0; q < 4; q++) {
            float4 v = sp[q];
            s[4*q]   = v.x * (1.f/32.f); s[4*q+1] = v.y * (1.f/32.f);
            s[4*q+2] = v.z * (1.f/32.f); s[4*q+3] = v.w * (1.f/32.f);
        }
#pragma unroll
        for (int i = 0; i < DO; i++) sq += s[i] * s[i];
        float scale = (sq / (1.f + sq)) * rsqrtf(sq + EPSQ);
#pragma unroll
        for (int i = 0; i < DO; i++) sV[b * 18 + i] = s[i] * scale;
    }
    __syncthreads();

    int lane = threadIdx.x & 31, w = threadIdx.x >> 5;
    int bh = w & 1, cw = w >> 1;
    int b = bh * 32 + lane;

    ull v2[8];
    {
        const ull* vp = (const ull*)&sV[b * 18];
#pragma unroll
        for (int p = 0; p < 8; p++) v2[p] = vp[p];
    }

#pragma unroll
    for (int t16 = 0; t16 < 16; t16++) {
        int cl = cw + 4 * t16;
        int c  = c0 + cl;
        const ulonglong2* wsv = (const ulonglong2*)&sW[cl * CSTRIDE];
        const float* xp = &g_xT3[(size_t)c * (DI * NB) + b];

        ull u2[8];
#pragma unroll
        for (int p = 0; p < 8; p++) u2[p] = 0ull;

#pragma unroll
        for (int j = 0; j < 8; j++) {
            float xf = xp[j * NB];
            ull xx = pack2(xf, xf);
            ulonglong2 wA = wsv[j * 4 + 0], wB = wsv[j * 4 + 1];
            ulonglong2 wC = wsv[j * 4 + 2], wD = wsv[j * 4 + 3];
            fma2(u2[0], wA.x, xx); fma2(u2[1], wA.y, xx);
            fma2(u2[2], wB.x, xx); fma2(u2[3], wB.y, xx);
            fma2(u2[4], wC.x, xx); fma2(u2[5], wC.y, xx);
            fma2(u2[6], wD.x, xx); fma2(u2[7], wD.y, xx);
        }
        ull d = 0ull;
#pragma unroll
        for (int p = 0; p < 8; p++) fma2(d, u2[p], v2[p]);
        float2 f = unpack2(d);
        g_a[((size_t)k * CIN + c) * NB + b] = f.x + f.y;
    }
}

// softmax over k at each (c,b), in place; also re-zeros g_s
__global__ void k_softmaxZ() {
    int idx = blockIdx.x * blockDim.x + threadIdx.x;
    if (idx < NB * NK * DO) g_s[idx] = 0.f;
    if (idx >= CIN * NB) return;
    float vals[NK]; float mx = -1e30f;
#pragma unroll
    for (int k = 0; k < NK; k++) {
        vals[k] = g_a[(size_t)k * (CIN * NB) + idx];
        mx = fmaxf(mx, vals[k]);
    }
    float sum = 0.f;
#pragma unroll
    for (int k = 0; k < NK; k++) { vals[k] = __expf(vals[k] - mx); sum += vals[k]; }
    float inv = 1.f / sum;
#pragma unroll
    for (int k = 0; k < NK; k++) g_a[(size_t)k * (CIN * NB) + idx] = vals[k] * inv;
}

// ---------- Pass E: s2[b,k,i] = sum_{c,j} W (cc x) ----------
__global__ void __launch_bounds__(256) k_passE(const float* __restrict__ W) {
    __shared__ __align__(16) float sb[8704];
    int k = blockIdx.y, c0 = blockIdx.x * CPB;
    load_w_tile(sb, W, k, c0);
    __syncthreads();

    int lane = threadIdx.x & 31, w = threadIdx.x >> 5;
    int bq = lane & 15, ih = lane >> 4;
    int b0 = 4 * bq;

    ull acc[4][4];
#pragma unroll
    for (int bi = 0; bi < 4; bi++)
#pragma unroll
        for (int p = 0; p < 4; p++) acc[bi][p] = 0ull;

#pragma unroll
    for (int it = 0; it < 8; it++) {
        int cl = 8 * w + it;
        int c  = c0 + cl;
        const float* wbase = &sb[cl * CSTRIDE + 8 * ih];
        const float4* xbase = (const float4*)&g_xT3[(size_t)c * (DI * NB) + b0];
        float4 cc = *(const float4*)&g_a[((size_t)k * CIN + c) * NB + b0];
#pragma unroll
        for (int j = 0; j < 8; j++) {
            float4 xv = xbase[j * 16];
            float m0 = xv.x * cc.x, m1 = xv.y * cc.y;
            float m2 = xv.z * cc.z, m3 = xv.w * cc.w;
            ull xx0 = pack2(m0, m0), xx1 = pack2(m1, m1);
            ull xx2 = pack2(m2, m2), xx3 = pack2(m3, m3);
            const ulonglong2* wp = (const ulonglong2*)(wbase + j * 16);
            ulonglong2 wA = wp[0], wB = wp[1];
            fma2(acc[0][0], wA.x, xx0); fma2(acc[0][1], wA.y, xx0);
            fma2(acc[0][2], wB.x, xx0); fma2(acc[0][3], wB.y, xx0);
            fma2(acc[1][0], wA.x, xx1); fma2(acc[1][1], wA.y, xx1);
            fma2(acc[1][2], wB.x, xx1); fma2(acc[1][3], wB.y, xx1);
            fma2(acc[2][0], wA.x, xx2); fma2(acc[2][1], wA.y, xx2);
            fma2(acc[2][2], wB.x, xx2); fma2(acc[2][3], wB.y, xx2);
            fma2(acc[3][0], wA.x, xx3); fma2(acc[3][1], wA.y, xx3);
            fma2(acc[3][2], wB.x, xx3); fma2(acc[3][3], wB.y, xx3);
        }
    }
    block_reduce_s(sb, acc, w, b0, ih, k);
}

// out = squash(s2)
__global__ void k_squashF(float* __restrict__ out) {
    int t = blockIdx.x * blockDim.x + threadIdx.x;
    if (t >= NB * NK) return;
    float s[DO]; float sq = 0.f;
#pragma unroll
    for (int i = 0; i < DO; i++) { s[i] = g_s[t * DO + i]; sq += s[i] * s[i]; }
    float scale = (sq / (1.f + sq)) * rsqrtf(sq + EPSQ);
#pragma unroll
    for (int i = 0; i < DO; i++) out[t * DO + i] = s[i] * scale;
}

extern "C" void kernel_launch(void* const* d_in, const int* in_sizes, int n_in,
                              void* d_out, int out_size) {
    const float* x = (const float*)d_in[0];
    const float* W = (const float*)d_in[1];
    if (n_in >= 2 && in_sizes[0] == 8388608 && in_sizes[1] == 1048576) {
        const float* t = x; x = W; W = t;   // defensive order swap
    }
    float* out = (float*)d_out;

    dim3 passGrid(CIN / CPB, NK);   // (32, 32)
    dim3 passBlk(256);

    k_zeroS    <<<128, 256>>>();                            // 1
    k_transpose<<<(CIN * DI * NB + 255) / 256, 256>>>(x);   // 2
    k_passA    <<<passGrid, passBlk>>>(W);                  // 3
    k_passC    <<<passGrid, passBlk>>>(W);                  // 4  <- ncu capture
    k_softmaxZ <<<(CIN * NB + 255) / 256, 256>>>();         // 5
    k_passE    <<<passGrid, passBlk>>>(W);                  // 6
    k_squashF  <<<(NB * NK + 127) / 128, 128>>>(out);       // 7
}

// round 13
// speedup vs baseline: 2.9345x; 1.0515x over previous
#include <cuda_runtime.h>
#include <math.h>

#define CIN 2048
#define NB  64
#define NK  32
#define DI  8
#define DO  16
#define EPSQ 1e-7f
#define CPB 64            // c per block
#define CSTRIDE 132       // smem stride per c for W tile (floats)

typedef unsigned long long ull;

// ---- scratch ----
__device__ float g_xT3[CIN * DI * NB];           // xT3[c][j][b] (4 MB)
__device__ float g_s  [NB * NK * DO];            // s accumulator
__device__ float g_a  [(size_t)NK * CIN * NB];   // aT[k][c][b] -> cc (16 MB)

// ---- f32x2 helpers ----
__device__ __forceinline__ void fma2(ull& d, ull a, ull b) {
    asm("fma.rn.f32x2 %0, %1, %2, %0;" : "+l"(d) : "l"(a), "l"(b));
}
__device__ __forceinline__ ull pack2(float lo, float hi) {
    ull r; asm("mov.b64 %0, {%1, %2};" : "=l"(r) : "f"(lo), "f"(hi)); return r;
}
__device__ __forceinline__ float2 unpack2(ull v) {
    float2 f; asm("mov.b64 {%0, %1}, %2;" : "=f"(f.x), "=f"(f.y) : "l"(v)); return f;
}

__global__ void k_zeroS() {
    int t = blockIdx.x * blockDim.x + threadIdx.x;
    if (t < NB * NK * DO) g_s[t] = 0.f;
}

// xT3[(c*8+j)*64+b] = x[b][c][j]
__global__ void k_transpose(const float* __restrict__ x) {
    int idx = blockIdx.x * blockDim.x + threadIdx.x;
    if (idx < CIN * DI * NB) {
        int b = idx & 63, j = (idx >> 6) & 7, c = idx >> 9;
        g_xT3[idx] = __ldg(&x[(b * CIN + c) * DI + j]);
    }
}

// Load W tile [64c][16i][8j] -> sW[c][j][i] (stride CSTRIDE)
__device__ __forceinline__ void load_w_tile(float* sW, const float* __restrict__ W,
                                            int k, int c0) {
    const float4* src = (const float4*)(W + ((size_t)k * CIN + c0) * (DO * DI));
#pragma unroll
    for (int r = 0; r < 8; r++) {
        int idx = threadIdx.x + r * 256;            // 2048 float4
        float4 v = __ldg(&src[idx]);
        int cp = idx >> 5, i = (idx >> 1) & 15, jq = idx & 1;
        float* d = &sW[cp * CSTRIDE + i];
        d[(4 * jq + 0) * 16] = v.x;
        d[(4 * jq + 1) * 16] = v.y;
        d[(4 * jq + 2) * 16] = v.z;
        d[(4 * jq + 3) * 16] = v.w;
    }
}

// block reduce acc[4][4] (4 b, one i-half) across 8 warps -> atomicAdd into g_s
__device__ __forceinline__ void block_reduce_s(float* sb, ull acc[4][4],
                                               int w, int b0, int ih, int k) {
    __syncthreads();
#pragma unroll
    for (int bi = 0; bi < 4; bi++) {
        float* row = &sb[(w * NB + b0 + bi) * 17 + 8 * ih];
#pragma unroll
        for (int p = 0; p < 4; p++) {
            float2 f = unpack2(acc[bi][p]);
            row[2 * p]     = f.x;
            row[2 * p + 1] = f.y;
        }
    }
    __syncthreads();
#pragma unroll
    for (int r = 0; r < 4; r++) {
        int u = threadIdx.x + 256 * r;              // 1024 outputs (b,i)
        int b = u >> 4, i = u & 15;
        float s = 0.f;
#pragma unroll
        for (int w2 = 0; w2 < 8; w2++)
            s += sb[(w2 * NB + b) * 17 + i];
        atomicAdd(&g_s[(b * NK + k) * DO + i], s);
    }
}

// ---------- Pass A: s1[b,k,i] = sum_{c,j} W x ----------
__global__ void __launch_bounds__(256) k_passA(const float* __restrict__ W) {
    __shared__ __align__(16) float sb[8704];
    int k = blockIdx.y, c0 = blockIdx.x * CPB;
    load_w_tile(sb, W, k, c0);
    __syncthreads();

    int lane = threadIdx.x & 31, w = threadIdx.x >> 5;
    int bq = lane & 15, ih = lane >> 4;
    int b0 = 4 * bq;

    ull acc[4][4];
#pragma unroll
    for (int bi = 0; bi < 4; bi++)
#pragma unroll
        for (int p = 0; p < 4; p++) acc[bi][p] = 0ull;

#pragma unroll
    for (int it = 0; it < 8; it++) {
        int cl = 8 * w + it;
        int c  = c0 + cl;
        const float* wbase = &sb[cl * CSTRIDE + 8 * ih];
        const float4* xbase = (const float4*)&g_xT3[(size_t)c * (DI * NB) + b0];
#pragma unroll
        for (int j = 0; j < 8; j++) {
            float4 xv = xbase[j * 16];
            ull xx0 = pack2(xv.x, xv.x), xx1 = pack2(xv.y, xv.y);
            ull xx2 = pack2(xv.z, xv.z), xx3 = pack2(xv.w, xv.w);
            const ulonglong2* wp = (const ulonglong2*)(wbase + j * 16);
            ulonglong2 wA = wp[0], wB = wp[1];
            fma2(acc[0][0], wA.x, xx0); fma2(acc[0][1], wA.y, xx0);
            fma2(acc[0][2], wB.x, xx0); fma2(acc[0][3], wB.y, xx0);
            fma2(acc[1][0], wA.x, xx1); fma2(acc[1][1], wA.y, xx1);
            fma2(acc[1][2], wB.x, xx1); fma2(acc[1][3], wB.y, xx1);
            fma2(acc[2][0], wA.x, xx2); fma2(acc[2][1], wA.y, xx2);
            fma2(acc[2][2], wB.x, xx2); fma2(acc[2][3], wB.y, xx2);
            fma2(acc[3][0], wA.x, xx3); fma2(acc[3][1], wA.y, xx3);
            fma2(acc[3][2], wB.x, xx3); fma2(acc[3][3], wB.y, xx3);
        }
    }
    block_reduce_s(sb, acc, w, b0, ih, k);
}

// ---------- Pass C: aT[k][c][b] = sum_i u * v1   (v1 squashed in prologue) ----------
__global__ void __launch_bounds__(256, 3) k_passC(const float* __restrict__ W) {
    __shared__ __align__(16) float sW[CPB * CSTRIDE];   // 8448 floats
    __shared__ __align__(16) float sV[NB * 18];         // squashed v1, stride 18
    int k = blockIdx.y, c0 = blockIdx.x * CPB;
    load_w_tile(sW, W, k, c0);

    // prologue: v1[b] = squash(s1[b,k]/32) into sV
    if (threadIdx.x < NB) {
        int b = threadIdx.x;
        const float4* sp = (const float4*)&g_s[(b * NK + k) * DO];
        float s[DO]; float sq = 0.f;
#pragma unroll
        for (int q = 0; q < 4; q++) {
            float4 v = sp[q];
            s[4*q]   = v.x * (1.f/32.f); s[4*q+1] = v.y * (1.f/32.f);
            s[4*q+2] = v.z * (1.f/32.f); s[4*q+3] = v.w * (1.f/32.f);
        }
#pragma unroll
        for (int i = 0; i < DO; i++) sq += s[i] * s[i];
        float scale = (sq / (1.f + sq)) * rsqrtf(sq + EPSQ);
#pragma unroll
        for (int i = 0; i < DO; i++) sV[b * 18 + i] = s[i] * scale;
    }
    __syncthreads();

    int lane = threadIdx.x & 31, w = threadIdx.x >> 5;
    int bq = lane & 15, ih = lane >> 4;
    int b0 = 4 * bq;

#pragma unroll
    for (int it = 0; it < 8; it++) {
        int cl = 8 * w + it;
        int c  = c0 + cl;
        const float* wbase = &sW[cl * CSTRIDE + 8 * ih];
        const float4* xbase = (const float4*)&g_xT3[(size_t)c * (DI * NB) + b0];

        ull u2[4][4];
#pragma unroll
        for (int bi = 0; bi < 4; bi++)
#pragma unroll
            for (int p = 0; p < 4; p++) u2[bi][p] = 0ull;

#pragma unroll
        for (int j = 0; j < 8; j++) {
            float4 xv = xbase[j * 16];
            ull xx0 = pack2(xv.x, xv.x), xx1 = pack2(xv.y, xv.y);
            ull xx2 = pack2(xv.z, xv.z), xx3 = pack2(xv.w, xv.w);
            const ulonglong2* wp = (const ulonglong2*)(wbase + j * 16);
            ulonglong2 wA = wp[0], wB = wp[1];
            fma2(u2[0][0], wA.x, xx0); fma2(u2[0][1], wA.y, xx0);
            fma2(u2[0][2], wB.x, xx0); fma2(u2[0][3], wB.y, xx0);
            fma2(u2[1][0], wA.x, xx1); fma2(u2[1][1], wA.y, xx1);
            fma2(u2[1][2], wB.x, xx1); fma2(u2[1][3], wB.y, xx1);
            fma2(u2[2][0], wA.x, xx2); fma2(u2[2][1], wA.y, xx2);
            fma2(u2[2][2], wB.x, xx2); fma2(u2[2][3], wB.y, xx2);
            fma2(u2[3][0], wA.x, xx3); fma2(u2[3][1], wA.y, xx3);
            fma2(u2[3][2], wB.x, xx3); fma2(u2[3][3], wB.y, xx3);
        }
        // dot with v1 (i-half) from smem, then combine halves
        float a[4];
#pragma unroll
        for (int bi = 0; bi < 4; bi++) {
            const ull* vp = (const ull*)&sV[(b0 + bi) * 18 + 8 * ih];
            ull d = 0ull;
            fma2(d, u2[bi][0], vp[0]);
            fma2(d, u2[bi][1], vp[1]);
            fma2(d, u2[bi][2], vp[2]);
            fma2(d, u2[bi][3], vp[3]);
            float2 f = unpack2(d);
            a[bi] = f.x + f.y;
        }
#pragma unroll
        for (int bi = 0; bi < 4; bi++)
            a[bi] += __shfl_xor_sync(0xFFFFFFFFu, a[bi], 16);
        if (ih == 0) {
            *(float4*)&g_a[((size_t)k * CIN + c) * NB + b0] =
                make_float4(a[0], a[1], a[2], a[3]);
        }
    }
}

// softmax over k at each (c,b), in place; also re-zeros g_s
__global__ void k_softmaxZ() {
    int idx = blockIdx.x * blockDim.x + threadIdx.x;
    if (idx < NB * NK * DO) g_s[idx] = 0.f;
    if (idx >= CIN * NB) return;
    float vals[NK]; float mx = -1e30f;
#pragma unroll
    for (int k = 0; k < NK; k++) {
        vals[k] = g_a[(size_t)k * (CIN * NB) + idx];
        mx = fmaxf(mx, vals[k]);
    }
    float sum = 0.f;
#pragma unroll
    for (int k = 0; k < NK; k++) { vals[k] = __expf(vals[k] - mx); sum += vals[k]; }
    float inv = 1.f / sum;
#pragma unroll
    for (int k = 0; k < NK; k++) g_a[(size_t)k * (CIN * NB) + idx] = vals[k] * inv;
}

// ---------- Pass E: s2[b,k,i] = sum_{c,j} W (cc x) ----------
__global__ void __launch_bounds__(256) k_passE(const float* __restrict__ W) {
    __shared__ __align__(16) float sb[8704];
    int k = blockIdx.y, c0 = blockIdx.x * CPB;
    load_w_tile(sb, W, k, c0);
    __syncthreads();

    int lane = threadIdx.x & 31, w = threadIdx.x >> 5;
    int bq = lane & 15, ih = lane >> 4;
    int b0 = 4 * bq;

    ull acc[4][4];
#pragma unroll
    for (int bi = 0; bi < 4; bi++)
#pragma unroll
        for (int p = 0; p < 4; p++) acc[bi][p] = 0ull;

#pragma unroll
    for (int it = 0; it < 8; it++) {
        int cl = 8 * w + it;
        int c  = c0 + cl;
        const float* wbase = &sb[cl * CSTRIDE + 8 * ih];
        const float4* xbase = (const float4*)&g_xT3[(size_t)c * (DI * NB) + b0];
        float4 cc = *(const float4*)&g_a[((size_t)k * CIN + c) * NB + b0];
#pragma unroll
        for (int j = 0; j < 8; j++) {
            float4 xv = xbase[j * 16];
            float m0 = xv.x * cc.x, m1 = xv.y * cc.y;
            float m2 = xv.z * cc.z, m3 = xv.w * cc.w;
            ull xx0 = pack2(m0, m0), xx1 = pack2(m1, m1);
            ull xx2 = pack2(m2, m2), xx3 = pack2(m3, m3);
            const ulonglong2* wp = (const ulonglong2*)(wbase + j * 16);
            ulonglong2 wA = wp[0], wB = wp[1];
            fma2(acc[0][0], wA.x, xx0); fma2(acc[0][1], wA.y, xx0);
            fma2(acc[0][2], wB.x, xx0); fma2(acc[0][3], wB.y, xx0);
            fma2(acc[1][0], wA.x, xx1); fma2(acc[1][1], wA.y, xx1);
            fma2(acc[1][2], wB.x, xx1); fma2(acc[1][3], wB.y, xx1);
            fma2(acc[2][0], wA.x, xx2); fma2(acc[2][1], wA.y, xx2);
            fma2(acc[2][2], wB.x, xx2); fma2(acc[2][3], wB.y, xx2);
            fma2(acc[3][0], wA.x, xx3); fma2(acc[3][1], wA.y, xx3);
            fma2(acc[3][2], wB.x, xx3); fma2(acc[3][3], wB.y, xx3);
        }
    }
    block_reduce_s(sb, acc, w, b0, ih, k);
}

// out = squash(s2)
__global__ void k_squashF(float* __restrict__ out) {
    int t = blockIdx.x * blockDim.x + threadIdx.x;
    if (t >= NB * NK) return;
    float s[DO]; float sq = 0.f;
#pragma unroll
    for (int i = 0; i < DO; i++) { s[i] = g_s[t * DO + i]; sq += s[i] * s[i]; }
    float scale = (sq / (1.f + sq)) * rsqrtf(sq + EPSQ);
#pragma unroll
    for (int i = 0; i < DO; i++) out[t * DO + i] = s[i] * scale;
}

extern "C" void kernel_launch(void* const* d_in, const int* in_sizes, int n_in,
                              void* d_out, int out_size) {
    const float* x = (const float*)d_in[0];
    const float* W = (const float*)d_in[1];
    if (n_in >= 2 && in_sizes[0] == 8388608 && in_sizes[1] == 1048576) {
        const float* t = x; x = W; W = t;   // defensive order swap
    }
    float* out = (float*)d_out;

    dim3 passGrid(CIN / CPB, NK);   // (32, 32)
    dim3 passBlk(256);

    k_zeroS    <<<128, 256>>>();                            // 1
    k_transpose<<<(CIN * DI * NB + 255) / 256, 256>>>(x);   // 2
    k_passA    <<<passGrid, passBlk>>>(W);                  // 3
    k_passC    <<<passGrid, passBlk>>>(W);                  // 4  <- ncu capture
    k_softmaxZ <<<(CIN * NB + 255) / 256, 256>>>();         // 5
    k_passE    <<<passGrid, passBlk>>>(W);                  // 6
    k_squashF  <<<(NB * NK + 127) / 128, 128>>>(out);       // 7
}